// round 2
// baseline (speedup 1.0000x reference)
#include <cuda_runtime.h>
#include <math.h>

#define BATCH   256
#define SEQ     257
#define HIDDEN  128
#define NPATCH  256
#define INPUT_D 588
#define DHEAD   64
#define NHEADS  2
#define MLPH    512
#define OUTD    1000

// ---------------- scratch (device globals; no allocations allowed) ----------
__device__ float g_out[BATCH * SEQ * HIDDEN];     // residual stream
__device__ float g_q[BATCH * SEQ * HIDDEN];
__device__ float g_k[BATCH * SEQ * HIDDEN];
__device__ float g_v[BATCH * SEQ * HIDDEN];
__device__ float g_pos[SEQ * HIDDEN];
__device__ float g_mapWT[INPUT_D * HIDDEN];       // [k][h]
__device__ float g_w1T[2 * HIDDEN * MLPH];        // [blk][k][t]
__device__ float g_w2T[2 * MLPH * HIDDEN];        // [blk][k][o]

// ---------------- positional embedding ---------------------------------------
__global__ void pos_kernel() {
    int i = blockIdx.x;      // seq position
    int j = threadIdx.x;     // hidden dim
    double e = (j % 2 == 0) ? (double)j / 128.0 : (double)(j - 1) / 128.0;
    double ang = (double)i / pow(10000.0, e);
    g_pos[i * HIDDEN + j] = (j % 2 == 0) ? (float)sin(ang) : (float)cos(ang);
}

// ---------------- weight transposes ------------------------------------------
__global__ void tr_map(const float* __restrict__ mapW) {
    int idx = blockIdx.x * blockDim.x + threadIdx.x;
    if (idx < HIDDEN * INPUT_D) {
        int h = idx / INPUT_D, k = idx % INPUT_D;
        g_mapWT[k * HIDDEN + h] = mapW[idx];
    }
}
__global__ void tr_w1(const float* __restrict__ w1) {
    int idx = blockIdx.x * blockDim.x + threadIdx.x;
    if (idx < 2 * MLPH * HIDDEN) {
        int blk = idx / (MLPH * HIDDEN);
        int r = idx % (MLPH * HIDDEN);
        int t = r / HIDDEN, k = r % HIDDEN;
        g_w1T[blk * HIDDEN * MLPH + k * MLPH + t] = w1[idx];
    }
}
__global__ void tr_w2(const float* __restrict__ w2) {
    int idx = blockIdx.x * blockDim.x + threadIdx.x;
    if (idx < 2 * HIDDEN * MLPH) {
        int blk = idx / (HIDDEN * MLPH);
        int r = idx % (HIDDEN * MLPH);
        int o = r / MLPH, k = r % MLPH;
        g_w2T[blk * MLPH * HIDDEN + k * HIDDEN + o] = w2[idx];
    }
}

// ---------------- cls token ---------------------------------------------------
__global__ void cls_kernel(const float* __restrict__ cls) {
    int b = blockIdx.x, h = threadIdx.x;
    g_out[(size_t)b * SEQ * HIDDEN + h] = cls[h] + g_pos[h];
}

// ---------------- patch embed: 8 patches per block ---------------------------
__global__ void patch_embed(const float* __restrict__ images,
                            const float* __restrict__ mapb) {
    int b = blockIdx.y;
    int p0 = blockIdx.x * 8;
    int h = threadIdx.x;                  // 128 threads
    __shared__ float s[8 * INPUT_D];

    for (int idx = h; idx < 8 * INPUT_D; idx += 128) {
        int j = idx / INPUT_D, k = idx % INPUT_D;
        int patch = p0 + j;
        int c = k / 196, r = k % 196, y = r / 14, x = r % 14;
        int py = patch >> 4, px = patch & 15;
        s[idx] = images[(((size_t)b * 3 + c) * 224 + (py * 14 + y)) * 224 + (px * 14 + x)];
    }
    __syncthreads();

    float acc[8];
    float bv = mapb[h];
#pragma unroll
    for (int j = 0; j < 8; j++) acc[j] = bv;

    for (int k = 0; k < INPUT_D; k += 4) {
        float w0 = g_mapWT[(k + 0) * HIDDEN + h];
        float w1 = g_mapWT[(k + 1) * HIDDEN + h];
        float w2 = g_mapWT[(k + 2) * HIDDEN + h];
        float w3 = g_mapWT[(k + 3) * HIDDEN + h];
#pragma unroll
        for (int j = 0; j < 8; j++) {
            float4 sv = *(const float4*)&s[j * INPUT_D + k];
            acc[j] += sv.x * w0 + sv.y * w1 + sv.z * w2 + sv.w * w3;
        }
    }
#pragma unroll
    for (int j = 0; j < 8; j++) {
        int seq = 1 + p0 + j;
        g_out[((size_t)b * SEQ + seq) * HIDDEN + h] = acc[j] + g_pos[seq * HIDDEN + h];
    }
}

// ---------------- LN1 + QKV projection (one token per block, 128 thr) ---------
__global__ void ln_qkv(const float* __restrict__ g, const float* __restrict__ bb,
                       const float* __restrict__ qW, const float* __restrict__ qb,
                       const float* __restrict__ kW, const float* __restrict__ kb,
                       const float* __restrict__ vW, const float* __restrict__ vb,
                       int blk) {
    int tok = blockIdx.x;
    int t = threadIdx.x;
    __shared__ float xs[HIDDEN];
    __shared__ float red[HIDDEN];

    float xv = g_out[(size_t)tok * HIDDEN + t];

    red[t] = xv; __syncthreads();
    for (int o = 64; o > 0; o >>= 1) { if (t < o) red[t] += red[t + o]; __syncthreads(); }
    float mu = red[0] * (1.0f / HIDDEN);
    __syncthreads();
    float d = xv - mu;
    red[t] = d * d; __syncthreads();
    for (int o = 64; o > 0; o >>= 1) { if (t < o) red[t] += red[t + o]; __syncthreads(); }
    float var = red[0] * (1.0f / HIDDEN);
    float rs = rsqrtf(var + 1e-5f);
    xs[t] = d * rs * g[blk * HIDDEN + t] + bb[blk * HIDDEN + t];
    __syncthreads();

    int head = t >> 6, e = t & 63;
    const float* qw = qW + (((size_t)blk * NHEADS + head) * 64 + e) * 64;
    const float* kw = kW + (((size_t)blk * NHEADS + head) * 64 + e) * 64;
    const float* vw = vW + (((size_t)blk * NHEADS + head) * 64 + e) * 64;
    float aq = qb[(blk * NHEADS + head) * 64 + e];
    float ak = kb[(blk * NHEADS + head) * 64 + e];
    float av = vb[(blk * NHEADS + head) * 64 + e];
    const float* xh = xs + head * 64;
    for (int dd = 0; dd < 64; dd += 4) {
        float4 xv4 = *(const float4*)&xh[dd];
        float4 q4 = *(const float4*)&qw[dd];
        float4 k4 = *(const float4*)&kw[dd];
        float4 v4 = *(const float4*)&vw[dd];
        aq += xv4.x * q4.x + xv4.y * q4.y + xv4.z * q4.z + xv4.w * q4.w;
        ak += xv4.x * k4.x + xv4.y * k4.y + xv4.z * k4.z + xv4.w * k4.w;
        av += xv4.x * v4.x + xv4.y * v4.y + xv4.z * v4.z + xv4.w * v4.w;
    }
    size_t o = (size_t)tok * HIDDEN + t;
    g_q[o] = aq; g_k[o] = ak; g_v[o] = av;
}

// ---------------- attention: 8 q-rows per block, 64 thr -----------------------
#define SC_PITCH 260
__global__ void attn_kernel() {
    int q0 = blockIdx.x * 8;
    int h = blockIdx.y;
    int b = blockIdx.z;
    int t = threadIdx.x;             // 64 threads, 2 warps
    int nq = SEQ - q0; if (nq > 8) nq = 8;

    __shared__ float qs[8][64];
    __shared__ float sc[8][SC_PITCH];
    __shared__ float red[2];

    for (int idx = t; idx < 8 * 64; idx += 64) {
        int j = idx >> 6, e = idx & 63;
        qs[j][e] = (j < nq) ? g_q[((size_t)b * SEQ + q0 + j) * HIDDEN + h * 64 + e] : 0.0f;
    }
    __syncthreads();

    const float scale = 0.125f;  // 1/sqrt(64)
    for (int kk = t; kk < SEQ; kk += 64) {
        const float* kp = g_k + ((size_t)b * SEQ + kk) * HIDDEN + h * 64;
        float a[8];
#pragma unroll
        for (int j = 0; j < 8; j++) a[j] = 0.0f;
        for (int e = 0; e < 64; e += 4) {
            float4 kv = *(const float4*)&kp[e];
#pragma unroll
            for (int j = 0; j < 8; j++) {
                float4 qv = *(const float4*)&qs[j][e];
                a[j] += qv.x * kv.x + qv.y * kv.y + qv.z * kv.z + qv.w * kv.w;
            }
        }
        for (int j = 0; j < nq; j++) sc[j][kk] = a[j] * scale;
    }
    __syncthreads();

    float sums[8];
    int w = t >> 5;
    for (int j = 0; j < nq; j++) {
        float m = -1e30f;
        for (int kk = t; kk < SEQ; kk += 64) m = fmaxf(m, sc[j][kk]);
        for (int o = 16; o > 0; o >>= 1) m = fmaxf(m, __shfl_xor_sync(0xffffffffu, m, o));
        if ((t & 31) == 0) red[w] = m;
        __syncthreads();
        m = fmaxf(red[0], red[1]);
        __syncthreads();
        float s = 0.0f;
        for (int kk = t; kk < SEQ; kk += 64) {
            float ex = __expf(sc[j][kk] - m);
            sc[j][kk] = ex;
            s += ex;
        }
        for (int o = 16; o > 0; o >>= 1) s += __shfl_xor_sync(0xffffffffu, s, o);
        if ((t & 31) == 0) red[w] = s;
        __syncthreads();
        sums[j] = red[0] + red[1];
        __syncthreads();
    }

    // AV: thread t = head-dim element
    float oacc[8];
#pragma unroll
    for (int j = 0; j < 8; j++) oacc[j] = 0.0f;
    for (int kk = 0; kk < SEQ; kk++) {
        float vv = g_v[((size_t)b * SEQ + kk) * HIDDEN + h * 64 + t];
#pragma unroll
        for (int j = 0; j < 8; j++) oacc[j] += sc[j][kk] * vv;
    }
    for (int j = 0; j < nq; j++) {
        size_t oi = ((size_t)b * SEQ + q0 + j) * HIDDEN + h * 64 + t;
        g_out[oi] += oacc[j] / sums[j];
    }
}

// ---------------- LN2 + MLP (+residual): 8 tokens per block, 512 thr ----------
__global__ void mlp_kernel(const float* __restrict__ g2, const float* __restrict__ b2g,
                           const float* __restrict__ b1, const float* __restrict__ b2,
                           int blk) {
    int tok0 = blockIdx.x * 8;
    int t = threadIdx.x;           // 512 threads
    __shared__ float xln[8][HIDDEN];
    __shared__ float hbuf[8][MLPH];
    __shared__ float psum[4][8][HIDDEN];

    int w = t >> 5, lane = t & 31;
    if (w < 8) {
        const float* row = g_out + (size_t)(tok0 + w) * HIDDEN;
        float v0 = row[lane], v1 = row[lane + 32], v2 = row[lane + 64], v3 = row[lane + 96];
        float s = v0 + v1 + v2 + v3;
        for (int o = 16; o > 0; o >>= 1) s += __shfl_xor_sync(0xffffffffu, s, o);
        float mu = s * (1.0f / HIDDEN);
        float d0 = v0 - mu, d1 = v1 - mu, d2 = v2 - mu, d3 = v3 - mu;
        float vs = d0 * d0 + d1 * d1 + d2 * d2 + d3 * d3;
        for (int o = 16; o > 0; o >>= 1) vs += __shfl_xor_sync(0xffffffffu, vs, o);
        float rs = rsqrtf(vs * (1.0f / HIDDEN) + 1e-5f);
        xln[w][lane]      = d0 * rs * g2[blk * HIDDEN + lane]      + b2g[blk * HIDDEN + lane];
        xln[w][lane + 32] = d1 * rs * g2[blk * HIDDEN + lane + 32] + b2g[blk * HIDDEN + lane + 32];
        xln[w][lane + 64] = d2 * rs * g2[blk * HIDDEN + lane + 64] + b2g[blk * HIDDEN + lane + 64];
        xln[w][lane + 96] = d3 * rs * g2[blk * HIDDEN + lane + 96] + b2g[blk * HIDDEN + lane + 96];
    }
    __syncthreads();

    // fc1 + GELU
    float acc[8];
    float bv = b1[blk * MLPH + t];
#pragma unroll
    for (int j = 0; j < 8; j++) acc[j] = bv;
    const float* w1p = g_w1T + (size_t)blk * HIDDEN * MLPH;
    for (int k = 0; k < HIDDEN; k += 4) {
        float wv0 = w1p[(k + 0) * MLPH + t];
        float wv1 = w1p[(k + 1) * MLPH + t];
        float wv2 = w1p[(k + 2) * MLPH + t];
        float wv3 = w1p[(k + 3) * MLPH + t];
#pragma unroll
        for (int j = 0; j < 8; j++) {
            float4 xv = *(const float4*)&xln[j][k];
            acc[j] += xv.x * wv0 + xv.y * wv1 + xv.z * wv2 + xv.w * wv3;
        }
    }
#pragma unroll
    for (int j = 0; j < 8; j++) {
        float hx = acc[j];
        hbuf[j][t] = hx * 0.5f * (1.0f + erff(hx * 0.70710678118f));
    }
    __syncthreads();

    // fc2 (split-K over 4 parts)
    int part = t >> 7, o = t & 127;
    const float* w2p = g_w2T + (size_t)blk * MLPH * HIDDEN + part * HIDDEN * HIDDEN;
    float a2[8];
#pragma unroll
    for (int j = 0; j < 8; j++) a2[j] = 0.0f;
    for (int k = 0; k < HIDDEN; k += 4) {
        float wv0 = w2p[(k + 0) * HIDDEN + o];
        float wv1 = w2p[(k + 1) * HIDDEN + o];
        float wv2 = w2p[(k + 2) * HIDDEN + o];
        float wv3 = w2p[(k + 3) * HIDDEN + o];
        int kk = part * HIDDEN + k;
#pragma unroll
        for (int j = 0; j < 8; j++) {
            float4 hv = *(const float4*)&hbuf[j][kk];
            a2[j] += hv.x * wv0 + hv.y * wv1 + hv.z * wv2 + hv.w * wv3;
        }
    }
#pragma unroll
    for (int j = 0; j < 8; j++) psum[part][j][o] = a2[j];
    __syncthreads();

    if (t < HIDDEN) {
        float bias = b2[blk * HIDDEN + t];
        for (int j = 0; j < 8; j++) {
            float y = psum[0][j][t] + psum[1][j][t] + psum[2][j][t] + psum[3][j][t] + bias;
            g_out[(size_t)(tok0 + j) * HIDDEN + t] += y;
        }
    }
}

// ---------------- classifier head + softmax ----------------------------------
__global__ void head_kernel(const float* __restrict__ headW, const float* __restrict__ headb,
                            float* __restrict__ out) {
    int b = blockIdx.x;
    int t = threadIdx.x;   // 256 threads, 8 warps
    __shared__ float clsv[HIDDEN];
    __shared__ float lg[OUTD];
    __shared__ float red[8];

    if (t < HIDDEN) clsv[t] = g_out[(size_t)b * SEQ * HIDDEN + t];
    __syncthreads();

    for (int o = t; o < OUTD; o += 256) {
        const float* wr = headW + (size_t)o * HIDDEN;
        float a = headb[o];
        for (int k = 0; k < HIDDEN; k += 4) {
            float4 cv = *(const float4*)&clsv[k];
            float4 wv = *(const float4*)&wr[k];
            a += cv.x * wv.x + cv.y * wv.y + cv.z * wv.z + cv.w * wv.w;
        }
        lg[o] = a;
    }
    __syncthreads();

    int w = t >> 5;
    float m = -1e30f;
    for (int o = t; o < OUTD; o += 256) m = fmaxf(m, lg[o]);
    for (int o = 16; o > 0; o >>= 1) m = fmaxf(m, __shfl_xor_sync(0xffffffffu, m, o));
    if ((t & 31) == 0) red[w] = m;
    __syncthreads();
    m = red[0];
    for (int i = 1; i < 8; i++) m = fmaxf(m, red[i]);
    __syncthreads();

    float s = 0.0f;
    for (int o = t; o < OUTD; o += 256) {
        float e = __expf(lg[o] - m);
        lg[o] = e;
        s += e;
    }
    for (int o = 16; o > 0; o >>= 1) s += __shfl_xor_sync(0xffffffffu, s, o);
    if ((t & 31) == 0) red[w] = s;
    __syncthreads();
    s = 0.0f;
    for (int i = 0; i < 8; i++) s += red[i];
    float inv = 1.0f / s;
    for (int o = t; o < OUTD; o += 256) out[(size_t)b * OUTD + o] = lg[o] * inv;
}

// ---------------- launch ------------------------------------------------------
extern "C" void kernel_launch(void* const* d_in, const int* in_sizes, int n_in,
                              void* d_out, int out_size) {
    const float* images = (const float*)d_in[0];
    const float* mapW   = (const float*)d_in[1];
    const float* mapb   = (const float*)d_in[2];
    const float* cls    = (const float*)d_in[3];
    const float* qW     = (const float*)d_in[4];
    const float* qb     = (const float*)d_in[5];
    const float* kW     = (const float*)d_in[6];
    const float* kb     = (const float*)d_in[7];
    const float* vW     = (const float*)d_in[8];
    const float* vb     = (const float*)d_in[9];
    const float* ln1g   = (const float*)d_in[10];
    const float* ln1b   = (const float*)d_in[11];
    const float* ln2g   = (const float*)d_in[12];
    const float* ln2b   = (const float*)d_in[13];
    const float* w1     = (const float*)d_in[14];
    const float* b1     = (const float*)d_in[15];
    const float* w2     = (const float*)d_in[16];
    const float* b2     = (const float*)d_in[17];
    const float* headW  = (const float*)d_in[18];
    const float* headb  = (const float*)d_in[19];
    float* out = (float*)d_out;

    pos_kernel<<<SEQ, HIDDEN>>>();
    tr_map<<<(HIDDEN * INPUT_D + 255) / 256, 256>>>(mapW);
    tr_w1<<<(2 * MLPH * HIDDEN + 255) / 256, 256>>>(w1);
    tr_w2<<<(2 * MLPH * HIDDEN + 255) / 256, 256>>>(w2);

    cls_kernel<<<BATCH, HIDDEN>>>(cls);
    patch_embed<<<dim3(NPATCH / 8, BATCH), 128>>>(images, mapb);

    for (int blk = 0; blk < 2; blk++) {
        ln_qkv<<<BATCH * SEQ, 128>>>(ln1g, ln1b, qW, qb, kW, kb, vW, vb, blk);
        attn_kernel<<<dim3((SEQ + 7) / 8, NHEADS, BATCH), 64>>>();
        mlp_kernel<<<BATCH * SEQ / 8, 512>>>(ln2g, ln2b, b1, b2, blk);
    }

    head_kernel<<<BATCH, 256>>>(headW, headb, out);
}

// round 3
// speedup vs baseline: 1.7593x; 1.7593x over previous
#include <cuda_runtime.h>
#include <math.h>

#define BATCH   256
#define SEQ     257
#define HIDDEN  128
#define NPATCH  256
#define INPUT_D 588
#define DHEAD   64
#define NHEADS  2
#define MLPH    512
#define OUTD    1000
#define NTOK    (BATCH * SEQ)   // 65792

// ---------------- scratch ----------------------------------------------------
__device__ float g_out[NTOK * HIDDEN];
__device__ float g_q[NTOK * HIDDEN];
__device__ float g_k[NTOK * HIDDEN];
__device__ float g_v[NTOK * HIDDEN];
__device__ float g_pos[SEQ * HIDDEN];
__device__ float g_mapWT[INPUT_D * HIDDEN];       // [k][h]
__device__ float g_w1T[2 * HIDDEN * MLPH];        // [blk][k][t]
__device__ float g_w2T[2 * MLPH * HIDDEN];        // [blk][k][o]
__device__ float g_wp[2 * NHEADS * DHEAD * 192];  // [blk][h][kdim][p*64+e]

// ---------------- positional embedding ---------------------------------------
__global__ void pos_kernel() {
    int i = blockIdx.x, j = threadIdx.x;
    double e = (j % 2 == 0) ? (double)j / 128.0 : (double)(j - 1) / 128.0;
    double ang = (double)i / pow(10000.0, e);
    g_pos[i * HIDDEN + j] = (j % 2 == 0) ? (float)sin(ang) : (float)cos(ang);
}

// ---------------- weight prep ------------------------------------------------
__global__ void tr_map(const float* __restrict__ mapW) {
    int idx = blockIdx.x * blockDim.x + threadIdx.x;
    if (idx < HIDDEN * INPUT_D) {
        int h = idx / INPUT_D, k = idx % INPUT_D;
        g_mapWT[k * HIDDEN + h] = mapW[idx];
    }
}
__global__ void tr_w1(const float* __restrict__ w1) {
    int idx = blockIdx.x * blockDim.x + threadIdx.x;
    if (idx < 2 * MLPH * HIDDEN) {
        int blk = idx / (MLPH * HIDDEN);
        int r = idx % (MLPH * HIDDEN);
        int t = r / HIDDEN, k = r % HIDDEN;
        g_w1T[blk * HIDDEN * MLPH + k * MLPH + t] = w1[idx];
    }
}
__global__ void tr_w2(const float* __restrict__ w2) {
    int idx = blockIdx.x * blockDim.x + threadIdx.x;
    if (idx < 2 * HIDDEN * MLPH) {
        int blk = idx / (HIDDEN * MLPH);
        int r = idx % (HIDDEN * MLPH);
        int o = r / MLPH, k = r % MLPH;
        g_w2T[blk * MLPH * HIDDEN + k * HIDDEN + o] = w2[idx];
    }
}
// pack qkv weights: g_wp[blk][h][d][c'] , c' = p*64+e, value = PW[blk][h][e][d]
__global__ void tr_qkv(const float* __restrict__ qW, const float* __restrict__ kW,
                       const float* __restrict__ vW) {
    int idx = blockIdx.x * blockDim.x + threadIdx.x;
    if (idx >= 2 * NHEADS * DHEAD * 192) return;
    int cp = idx % 192;
    int d  = (idx / 192) % DHEAD;
    int h  = (idx / (192 * DHEAD)) % NHEADS;
    int blk = idx / (192 * DHEAD * NHEADS);
    int p = cp / 64, e = cp % 64;
    const float* src = (p == 0) ? qW : (p == 1) ? kW : vW;
    g_wp[idx] = src[(((size_t)blk * NHEADS + h) * DHEAD + e) * DHEAD + d];
}

// ---------------- cls token ---------------------------------------------------
__global__ void cls_kernel(const float* __restrict__ cls) {
    int b = blockIdx.x, h = threadIdx.x;
    g_out[(size_t)b * SEQ * HIDDEN + h] = cls[h] + g_pos[h];
}

// ---------------- patch embed: 16 patches / block, 128 thr --------------------
__global__ void patch_embed(const float* __restrict__ images,
                            const float* __restrict__ mapb) {
    int b = blockIdx.y;
    int p0 = blockIdx.x * 16;
    int h = threadIdx.x;
    __shared__ float s[16 * INPUT_D];

    for (int idx = h; idx < 16 * INPUT_D; idx += 128) {
        int j = idx / INPUT_D, k = idx % INPUT_D;
        int patch = p0 + j;
        int c = k / 196, r = k % 196, y = r / 14, x = r % 14;
        int py = patch >> 4, px = patch & 15;
        s[idx] = images[(((size_t)b * 3 + c) * 224 + (py * 14 + y)) * 224 + (px * 14 + x)];
    }
    __syncthreads();

    float acc[16];
    float bv = mapb[h];
#pragma unroll
    for (int j = 0; j < 16; j++) acc[j] = bv;

    for (int k = 0; k < INPUT_D; k += 4) {
        float w0 = g_mapWT[(k + 0) * HIDDEN + h];
        float w1 = g_mapWT[(k + 1) * HIDDEN + h];
        float w2 = g_mapWT[(k + 2) * HIDDEN + h];
        float w3 = g_mapWT[(k + 3) * HIDDEN + h];
#pragma unroll
        for (int j = 0; j < 16; j++) {
            float4 sv = *(const float4*)&s[j * INPUT_D + k];
            acc[j] += sv.x * w0 + sv.y * w1 + sv.z * w2 + sv.w * w3;
        }
    }
#pragma unroll
    for (int j = 0; j < 16; j++) {
        int seq = 1 + p0 + j;
        g_out[((size_t)b * SEQ + seq) * HIDDEN + h] = acc[j] + g_pos[seq * HIDDEN + h];
    }
}

// ---------------- LN1 + QKV: 16 tokens / block, 384 thr ----------------------
__global__ void ln_qkv(const float* __restrict__ g, const float* __restrict__ bb,
                       const float* __restrict__ qb, const float* __restrict__ kb,
                       const float* __restrict__ vb, int blk) {
    int tok0 = blockIdx.x * 16;
    int t = threadIdx.x;
    int w = t >> 5, lane = t & 31;
    __shared__ float xln[16][HIDDEN];

    // LayerNorm: 12 warps cover 16 tokens
    for (int j = w; j < 16; j += 12) {
        const float* row = g_out + (size_t)(tok0 + j) * HIDDEN;
        float v0 = row[lane], v1 = row[lane + 32], v2 = row[lane + 64], v3 = row[lane + 96];
        float s = v0 + v1 + v2 + v3;
        for (int o = 16; o > 0; o >>= 1) s += __shfl_xor_sync(0xffffffffu, s, o);
        float mu = s * (1.0f / HIDDEN);
        float d0 = v0 - mu, d1 = v1 - mu, d2 = v2 - mu, d3 = v3 - mu;
        float vs = d0 * d0 + d1 * d1 + d2 * d2 + d3 * d3;
        for (int o = 16; o > 0; o >>= 1) vs += __shfl_xor_sync(0xffffffffu, vs, o);
        float rs = rsqrtf(vs * (1.0f / HIDDEN) + 1e-5f);
        xln[j][lane]      = d0 * rs * g[blk * HIDDEN + lane]      + bb[blk * HIDDEN + lane];
        xln[j][lane + 32] = d1 * rs * g[blk * HIDDEN + lane + 32] + bb[blk * HIDDEN + lane + 32];
        xln[j][lane + 64] = d2 * rs * g[blk * HIDDEN + lane + 64] + bb[blk * HIDDEN + lane + 64];
        xln[j][lane + 96] = d3 * rs * g[blk * HIDDEN + lane + 96] + bb[blk * HIDDEN + lane + 96];
    }
    __syncthreads();

    // GEMM: thread t -> projection p, column c. Warp-uniform head h.
    int p = t >> 7;            // 0=q 1=k 2=v
    int c = t & 127;           // output column within projection
    int h = c >> 6, e = c & 63;
    int cp = p * 64 + e;
    const float* wrow = g_wp + ((size_t)(blk * NHEADS + h) * DHEAD) * 192 + cp;
    const float* bsrc = (p == 0) ? qb : (p == 1) ? kb : vb;
    float bias = bsrc[blk * HIDDEN + c];

    float acc[16];
#pragma unroll
    for (int j = 0; j < 16; j++) acc[j] = bias;

    int xoff = h * 64;
    for (int kd = 0; kd < 64; kd += 4) {
        float w0 = wrow[(kd + 0) * 192];
        float w1 = wrow[(kd + 1) * 192];
        float w2 = wrow[(kd + 2) * 192];
        float w3 = wrow[(kd + 3) * 192];
#pragma unroll
        for (int j = 0; j < 16; j++) {
            float4 xv = *(const float4*)&xln[j][xoff + kd];
            acc[j] += xv.x * w0 + xv.y * w1 + xv.z * w2 + xv.w * w3;
        }
    }
    float* dst = (p == 0) ? g_q : (p == 1) ? g_k : g_v;
#pragma unroll
    for (int j = 0; j < 16; j++)
        dst[(size_t)(tok0 + j) * HIDDEN + c] = acc[j];
}

// ---------------- attention: 32 q-rows / block, 128 thr ----------------------
#define QT 32
#define SC_PITCH 264
__global__ void attn_kernel() {
    int q0 = blockIdx.x * QT;
    int h = blockIdx.y;
    int b = blockIdx.z;
    int t = threadIdx.x;
    int w = t >> 5, lane = t & 31;
    int nq = SEQ - q0; if (nq > QT) nq = QT;

    __shared__ float qs[QT][64];
    __shared__ float sc[QT][SC_PITCH];
    __shared__ float sums_s[QT];

    for (int idx = t; idx < QT * 64; idx += 128) {
        int j = idx >> 6, e = idx & 63;
        qs[j][e] = (j < nq) ? g_q[((size_t)b * SEQ + q0 + j) * HIDDEN + h * 64 + e] : 0.0f;
    }
    __syncthreads();

    const float scale = 0.125f;
    for (int kk = t; kk < SEQ; kk += 128) {
        const float* kp = g_k + ((size_t)b * SEQ + kk) * HIDDEN + h * 64;
        float a[QT];
#pragma unroll
        for (int j = 0; j < QT; j++) a[j] = 0.0f;
        for (int e = 0; e < 64; e += 4) {
            float4 kv = *(const float4*)&kp[e];
#pragma unroll
            for (int j = 0; j < QT; j++) {
                float4 qv = *(const float4*)&qs[j][e];
                a[j] += qv.x * kv.x + qv.y * kv.y + qv.z * kv.z + qv.w * kv.w;
            }
        }
        for (int j = 0; j < nq; j++) sc[j][kk] = a[j] * scale;
    }
    __syncthreads();

    // softmax: warp w handles rows w*8 .. w*8+7
    for (int r = 0; r < 8; r++) {
        int j = w * 8 + r;
        if (j >= nq) break;
        float m = -1e30f;
        for (int kk = lane; kk < SEQ; kk += 32) m = fmaxf(m, sc[j][kk]);
        for (int o = 16; o > 0; o >>= 1) m = fmaxf(m, __shfl_xor_sync(0xffffffffu, m, o));
        float s = 0.0f;
        for (int kk = lane; kk < SEQ; kk += 32) {
            float ex = __expf(sc[j][kk] - m);
            sc[j][kk] = ex;
            s += ex;
        }
        for (int o = 16; o > 0; o >>= 1) s += __shfl_xor_sync(0xffffffffu, s, o);
        if (lane == 0) sums_s[j] = s;
    }
    __syncthreads();

    // AV: 2 groups of 64 threads, each handles 16 rows
    int e = t & 63, grp = t >> 6;
    int j0 = grp * 16;
    float oacc[16];
#pragma unroll
    for (int j = 0; j < 16; j++) oacc[j] = 0.0f;
    for (int kk = 0; kk < SEQ; kk++) {
        float vv = g_v[((size_t)b * SEQ + kk) * HIDDEN + h * 64 + e];
#pragma unroll
        for (int j = 0; j < 16; j++) oacc[j] += sc[j0 + j][kk] * vv;
    }
    for (int j = 0; j < 16; j++) {
        int jr = j0 + j;
        if (jr < nq) {
            size_t oi = ((size_t)b * SEQ + q0 + jr) * HIDDEN + h * 64 + e;
            g_out[oi] += oacc[j] / sums_s[jr];
        }
    }
}

// ---------------- LN2 + MLP (+residual): 16 tokens / block, 512 thr -----------
__global__ void mlp_kernel(const float* __restrict__ g2, const float* __restrict__ b2g,
                           const float* __restrict__ b1, const float* __restrict__ b2,
                           int blk) {
    int tok0 = blockIdx.x * 16;
    int t = threadIdx.x;
    int w = t >> 5, lane = t & 31;
    __shared__ float xln[16][HIDDEN];
    __shared__ float hbuf[16][MLPH];

    // LN: 16 warps, warp per token
    {
        const float* row = g_out + (size_t)(tok0 + w) * HIDDEN;
        float v0 = row[lane], v1 = row[lane + 32], v2 = row[lane + 64], v3 = row[lane + 96];
        float s = v0 + v1 + v2 + v3;
        for (int o = 16; o > 0; o >>= 1) s += __shfl_xor_sync(0xffffffffu, s, o);
        float mu = s * (1.0f / HIDDEN);
        float d0 = v0 - mu, d1 = v1 - mu, d2 = v2 - mu, d3 = v3 - mu;
        float vs = d0 * d0 + d1 * d1 + d2 * d2 + d3 * d3;
        for (int o = 16; o > 0; o >>= 1) vs += __shfl_xor_sync(0xffffffffu, vs, o);
        float rs = rsqrtf(vs * (1.0f / HIDDEN) + 1e-5f);
        xln[w][lane]      = d0 * rs * g2[blk * HIDDEN + lane]      + b2g[blk * HIDDEN + lane];
        xln[w][lane + 32] = d1 * rs * g2[blk * HIDDEN + lane + 32] + b2g[blk * HIDDEN + lane + 32];
        xln[w][lane + 64] = d2 * rs * g2[blk * HIDDEN + lane + 64] + b2g[blk * HIDDEN + lane + 64];
        xln[w][lane + 96] = d3 * rs * g2[blk * HIDDEN + lane + 96] + b2g[blk * HIDDEN + lane + 96];
    }
    __syncthreads();

    // fc1 + GELU: thread t -> hidden col t, 16 tokens
    float acc[16];
    float bv = b1[blk * MLPH + t];
#pragma unroll
    for (int j = 0; j < 16; j++) acc[j] = bv;
    const float* w1p = g_w1T + (size_t)blk * HIDDEN * MLPH;
    for (int k = 0; k < HIDDEN; k += 4) {
        float wv0 = w1p[(k + 0) * MLPH + t];
        float wv1 = w1p[(k + 1) * MLPH + t];
        float wv2 = w1p[(k + 2) * MLPH + t];
        float wv3 = w1p[(k + 3) * MLPH + t];
#pragma unroll
        for (int j = 0; j < 16; j++) {
            float4 xv = *(const float4*)&xln[j][k];
            acc[j] += xv.x * wv0 + xv.y * wv1 + xv.z * wv2 + xv.w * wv3;
        }
    }
#pragma unroll
    for (int j = 0; j < 16; j++) {
        float hx = acc[j];
        hbuf[j][t] = hx * 0.5f * (1.0f + erff(hx * 0.70710678118f));
    }
    __syncthreads();

    // fc2: thread t -> out col o = t&127, token group grp = t>>7 (4 tokens each)
    int o = t & 127, grp = t >> 7;
    int jb = grp * 4;
    const float* w2p = g_w2T + (size_t)blk * MLPH * HIDDEN;
    float a2[4];
#pragma unroll
    for (int j = 0; j < 4; j++) a2[j] = 0.0f;
    for (int k = 0; k < MLPH; k += 4) {
        float wv0 = w2p[(k + 0) * HIDDEN + o];
        float wv1 = w2p[(k + 1) * HIDDEN + o];
        float wv2 = w2p[(k + 2) * HIDDEN + o];
        float wv3 = w2p[(k + 3) * HIDDEN + o];
#pragma unroll
        for (int j = 0; j < 4; j++) {
            float4 hv = *(const float4*)&hbuf[jb + j][k];
            a2[j] += hv.x * wv0 + hv.y * wv1 + hv.z * wv2 + hv.w * wv3;
        }
    }
    float bias = b2[blk * HIDDEN + o];
#pragma unroll
    for (int j = 0; j < 4; j++)
        g_out[(size_t)(tok0 + jb + j) * HIDDEN + o] += a2[j] + bias;
}

// ---------------- classifier head + softmax ----------------------------------
__global__ void head_kernel(const float* __restrict__ headW, const float* __restrict__ headb,
                            float* __restrict__ out) {
    int b = blockIdx.x;
    int t = threadIdx.x;
    __shared__ float clsv[HIDDEN];
    __shared__ float lg[OUTD];
    __shared__ float red[8];

    if (t < HIDDEN) clsv[t] = g_out[(size_t)b * SEQ * HIDDEN + t];
    __syncthreads();

    for (int o = t; o < OUTD; o += 256) {
        const float* wr = headW + (size_t)o * HIDDEN;
        float a = headb[o];
        for (int k = 0; k < HIDDEN; k += 4) {
            float4 cv = *(const float4*)&clsv[k];
            float4 wv = *(const float4*)&wr[k];
            a += cv.x * wv.x + cv.y * wv.y + cv.z * wv.z + cv.w * wv.w;
        }
        lg[o] = a;
    }
    __syncthreads();

    int w = t >> 5;
    float m = -1e30f;
    for (int o = t; o < OUTD; o += 256) m = fmaxf(m, lg[o]);
    for (int o = 16; o > 0; o >>= 1) m = fmaxf(m, __shfl_xor_sync(0xffffffffu, m, o));
    if ((t & 31) == 0) red[w] = m;
    __syncthreads();
    m = red[0];
    for (int i = 1; i < 8; i++) m = fmaxf(m, red[i]);
    __syncthreads();

    float s = 0.0f;
    for (int o = t; o < OUTD; o += 256) {
        float e = __expf(lg[o] - m);
        lg[o] = e;
        s += e;
    }
    for (int o = 16; o > 0; o >>= 1) s += __shfl_xor_sync(0xffffffffu, s, o);
    if ((t & 31) == 0) red[w] = s;
    __syncthreads();
    s = 0.0f;
    for (int i = 0; i < 8; i++) s += red[i];
    float inv = 1.0f / s;
    for (int o = t; o < OUTD; o += 256) out[(size_t)b * OUTD + o] = lg[o] * inv;
}

// ---------------- launch ------------------------------------------------------
extern "C" void kernel_launch(void* const* d_in, const int* in_sizes, int n_in,
                              void* d_out, int out_size) {
    const float* images = (const float*)d_in[0];
    const float* mapW   = (const float*)d_in[1];
    const float* mapb   = (const float*)d_in[2];
    const float* cls    = (const float*)d_in[3];
    const float* qW     = (const float*)d_in[4];
    const float* qb     = (const float*)d_in[5];
    const float* kW     = (const float*)d_in[6];
    const float* kb     = (const float*)d_in[7];
    const float* vW     = (const float*)d_in[8];
    const float* vb     = (const float*)d_in[9];
    const float* ln1g   = (const float*)d_in[10];
    const float* ln1b   = (const float*)d_in[11];
    const float* ln2g   = (const float*)d_in[12];
    const float* ln2b   = (const float*)d_in[13];
    const float* w1     = (const float*)d_in[14];
    const float* b1     = (const float*)d_in[15];
    const float* w2     = (const float*)d_in[16];
    const float* b2     = (const float*)d_in[17];
    const float* headW  = (const float*)d_in[18];
    const float* headb  = (const float*)d_in[19];
    float* out = (float*)d_out;

    pos_kernel<<<SEQ, HIDDEN>>>();
    tr_map<<<(HIDDEN * INPUT_D + 255) / 256, 256>>>(mapW);
    tr_w1<<<(2 * MLPH * HIDDEN + 255) / 256, 256>>>(w1);
    tr_w2<<<(2 * HIDDEN * MLPH + 255) / 256, 256>>>(w2);
    tr_qkv<<<(2 * NHEADS * DHEAD * 192 + 255) / 256, 256>>>(qW, kW, vW);

    cls_kernel<<<BATCH, HIDDEN>>>(cls);
    patch_embed<<<dim3(NPATCH / 16, BATCH), 128>>>(images, mapb);

    for (int blk = 0; blk < 2; blk++) {
        ln_qkv<<<NTOK / 16, 384>>>(ln1g, ln1b, qb, kb, vb, blk);
        attn_kernel<<<dim3((SEQ + QT - 1) / QT, NHEADS, BATCH), 128>>>();
        mlp_kernel<<<NTOK / 16, 512>>>(ln2g, ln2b, b1, b2, blk);
    }

    head_kernel<<<BATCH, 256>>>(headW, headb, out);
}